// round 5
// baseline (speedup 1.0000x reference)
#include <cuda_runtime.h>
#include <cuda_bf16.h>
#include <cstdint>

#define DN 256          // nodes
#define HN 64           // hidden
#define BN 8192         // batch
#define ROWS 64         // rows per CTA
#define THREADS 512     // 16 warps
#define NBLOCKS (BN / ROWS)   // 128
#define CHJ 64          // j-chunk (weight tile rows)

typedef unsigned long long u64;

// Plain masked transposed weights (identical layout to the R2 PASSING kernel):
// g_Wt[i][j][k] = W1[i,k,j] * sigmoid(adj_logits[j,i]) * (j != i).  16.8 MB.
__device__ __align__(256) float g_Wt[(size_t)DN * DN * HN];

// ---------------- packed f32x2 helpers (sm_103a) ----------------
__device__ __forceinline__ u64 pack2(float lo, float hi) {
    u64 r;
    asm("mov.b64 %0, {%1, %2};" : "=l"(r) : "f"(lo), "f"(hi));
    return r;
}
__device__ __forceinline__ void unpack2(u64 v, float& lo, float& hi) {
    asm("mov.b64 {%0, %1}, %2;" : "=f"(lo), "=f"(hi) : "l"(v));
}
__device__ __forceinline__ u64 fma2(u64 a, u64 b, u64 c) {
    u64 d;
    asm("fma.rn.f32x2 %0, %1, %2, %3;" : "=l"(d) : "l"(a), "l"(b), "l"(c));
    return d;
}

__device__ __forceinline__ void cp_async16(void* smem_dst, const void* gsrc) {
    uint32_t s = (uint32_t)__cvta_generic_to_shared(smem_dst);
    asm volatile("cp.async.cg.shared.global [%0], [%1], 16;"
                 :: "r"(s), "l"(gsrc) : "memory");
}
__device__ __forceinline__ void cp_commit() {
    asm volatile("cp.async.commit_group;" ::: "memory");
}
__device__ __forceinline__ void cp_wait_all() {
    asm volatile("cp.async.wait_group 0;" ::: "memory");
}

__device__ __forceinline__ int nch_of(int i) {      // weight chunks for node i
    int jmax = (i + 3) & ~3;
    return (jmax + CHJ - 1) >> 6;
}

// ---------------- precompute (identical to the R2 passing version) ----------------
__global__ void precompute_kernel(const float* __restrict__ W1,
                                  const float* __restrict__ adj_logits) {
    int i = blockIdx.x;
    __shared__ float tile[64][65];
    __shared__ float asig[64];
    const float* W1i = W1 + (size_t)i * HN * DN;   // [H][D], j fastest
    float* Wti = g_Wt + (size_t)i * DN * HN;       // [D][H], k fastest

    for (int j0 = 0; j0 < DN; j0 += 64) {
        for (int idx = threadIdx.x; idx < 64 * 64; idx += blockDim.x) {
            int k = idx >> 6, jj = idx & 63;
            tile[k][jj] = W1i[k * DN + j0 + jj];          // coalesced read
        }
        if (threadIdx.x < 64) {
            int j = j0 + threadIdx.x;
            float l = adj_logits[j * DN + i];
            float s = 1.0f / (1.0f + __expf(-l));
            asig[threadIdx.x] = (j == i) ? 0.0f : s;
        }
        __syncthreads();
        for (int idx = threadIdx.x; idx < 64 * 64; idx += blockDim.x) {
            int jj = idx >> 6, k = idx & 63;
            Wti[(j0 + jj) * HN + k] = tile[k][jj] * asig[jj];  // coalesced write
        }
        __syncthreads();
    }
}

// ---------------- main kernel ----------------
// Mapping: warp wid (0..15) owns batch rows [4*wid, 4*wid+4); lane owns hidden
// k-pair (2*lane, 2*lane+1).  z is stored DUPLICATED in smem: zd[col][row] =
// (z, z) as u64.  Per j per warp: 1 lane-distinct LDS.64 (weight pair, natural
// packing) + 4 broadcast LDS.64 (z) + 4 FFMA2.  k-reduction = warp butterfly.
//
// smem: zd u64[DN][ROWS] (128 KB) | Wb float[2][CHJ*HN] (2 x 16 KB) = 160 KB
extern __shared__ u64 smem_u64[];

__global__ void __launch_bounds__(THREADS, 1)
scm_kernel(const float* __restrict__ noise,
           const float* __restrict__ b1,
           const float* __restrict__ W2,
           const float* __restrict__ b2,
           const float* __restrict__ log_sigma,
           float* __restrict__ out) {
    u64*   zd = smem_u64;                        // [DN][ROWS] duplicated pairs
    float* Wb = (float*)(smem_u64 + DN * ROWS);  // 2 x [CHJ][HN] plain floats

    const int tid  = threadIdx.x;
    const int lane = tid & 31;
    const int wid  = tid >> 5;       // 0..15
    const int r0   = 4 * wid;        // this warp's 4 batch rows
    const int kk   = 2 * lane;       // this lane's k-pair
    const int row0 = blockIdx.x * ROWS;

    // zero zd (padding columns >= i must read as zero)
    for (int idx = tid; idx < DN * ROWS; idx += THREADS) zd[idx] = 0ull;
    __syncthreads();   // node-0 writers differ from zeroers

    // prefetch first tile of the stream: (node 1, chunk 0) -> buffer 0
    {
        const float4* src = (const float4*)(g_Wt + (size_t)1 * DN * HN);
        float4* dst = (float4*)Wb;
        cp_async16(dst + tid, src + tid);
        cp_async16(dst + THREADS + tid, src + THREADS + tid);
        cp_commit();
    }
    int pi = 2, pc = 0;        // generator already past tile (1,0): nch_of(1)=1
    int pb = 1, cb = 0;        // prefetch / consume buffer toggles

    for (int i = 0; i < DN; ++i) {
        const int jmax = (i + 3) & ~3;
        const int nch  = (jmax + CHJ - 1) >> 6;

        // node-scope params (latency hidden under the j-loop)
        float2 b1p = __ldg((const float2*)(b1 + i * HN + kk));
        float2 w2p = __ldg((const float2*)(W2 + i * HN + kk));
        float  b2v  = __ldg(b2 + i);
        float  sigv = __expf(__ldg(log_sigma + i));
        float  nv = 0.0f;
        if (lane < 4)
            nv = __ldg(noise + (size_t)(row0 + r0 + lane) * DN + i);

        u64 acc[4];
        #pragma unroll
        for (int r = 0; r < 4; ++r) acc[r] = 0ull;

        for (int c = 0; c < nch; ++c) {
            cp_wait_all();
            __syncthreads();          // tile (i,c) ready in buffer cb;
                                      // c==0 also publishes z column i-1

            // prefetch the next stream tile into the other buffer
            if (pi < DN) {
                const float4* src =
                    (const float4*)(g_Wt + ((size_t)pi * DN + pc * CHJ) * HN);
                float4* dst = (float4*)(Wb + (size_t)pb * CHJ * HN);
                cp_async16(dst + tid, src + tid);
                cp_async16(dst + THREADS + tid, src + THREADS + tid);
                pc++; if (pc >= nch_of(pi)) { pi++; pc = 0; }
                pb ^= 1;
            }
            cp_commit();

            int jend = jmax - c * CHJ; if (jend > CHJ) jend = CHJ;
            const float* W_s = Wb + (size_t)cb * CHJ * HN;
            const u64* zcol = zd + (size_t)c * CHJ * ROWS + r0;
            cb ^= 1;

            #pragma unroll 4
            for (int j = 0; j < jend; ++j) {
                // lane-distinct natural weight pair (w_2l, w_2l+1): LDS.64
                u64 wp = *(const u64*)(W_s + j * HN + kk);
                // 4 broadcast z pairs for this warp's rows
                u64 z0 = zcol[j * ROWS + 0];
                u64 z1 = zcol[j * ROWS + 1];
                u64 z2 = zcol[j * ROWS + 2];
                u64 z3 = zcol[j * ROWS + 3];
                acc[0] = fma2(wp, z0, acc[0]);
                acc[1] = fma2(wp, z1, acc[1]);
                acc[2] = fma2(wp, z2, acc[2]);
                acc[3] = fma2(wp, z3, acc[3]);
            }
        }

        // epilogue: h = silu(acc + b1), dot with w2 (lane covers 2 k), then
        // full-warp butterfly -> every lane holds the row sum.
        float sums0, sums1, sums2, sums3;
        {
            float a0, a1, x0, x1, s;
            #define ROW_REDUCE(ACC, OUT)                                        \
                unpack2(ACC, a0, a1);                                           \
                x0 = a0 + b1p.x; x1 = a1 + b1p.y;                               \
                s  = __fdividef(x0, 1.0f + __expf(-x0)) * w2p.x                 \
                   + __fdividef(x1, 1.0f + __expf(-x1)) * w2p.y;                \
                s += __shfl_xor_sync(0xffffffffu, s, 16);                       \
                s += __shfl_xor_sync(0xffffffffu, s, 8);                        \
                s += __shfl_xor_sync(0xffffffffu, s, 4);                        \
                s += __shfl_xor_sync(0xffffffffu, s, 2);                        \
                s += __shfl_xor_sync(0xffffffffu, s, 1);                        \
                OUT = s;
            ROW_REDUCE(acc[0], sums0)
            ROW_REDUCE(acc[1], sums1)
            ROW_REDUCE(acc[2], sums2)
            ROW_REDUCE(acc[3], sums3)
            #undef ROW_REDUCE
        }

        __syncthreads();   // all padding reads of column i done before write
        if (lane < 4) {
            float sv = (lane == 0) ? sums0 : (lane == 1) ? sums1
                     : (lane == 2) ? sums2 : sums3;
            float val = sv + b2v + sigv * nv;
            zd[(size_t)i * ROWS + r0 + lane] = pack2(val, val);
        }
        // next node's c==0 wait+sync publishes z column i to all readers
    }

    __syncthreads();   // publish final z columns written by other warps

    // write out z: global-coalesced (take .lo of each duplicated pair)
    for (int idx = tid; idx < ROWS * DN; idx += THREADS) {
        int r = idx >> 8;        // 0..63
        int j = idx & 255;       // 0..255
        float lo, hi;
        unpack2(zd[(size_t)j * ROWS + r], lo, hi);
        out[(size_t)(row0 + r) * DN + j] = lo;
    }
}

extern "C" void kernel_launch(void* const* d_in, const int* in_sizes, int n_in,
                              void* d_out, int out_size) {
    const float* noise      = (const float*)d_in[0];
    const float* adj_logits = (const float*)d_in[1];
    const float* W1         = (const float*)d_in[2];
    const float* b1         = (const float*)d_in[3];
    const float* W2         = (const float*)d_in[4];
    const float* b2         = (const float*)d_in[5];
    const float* log_sigma  = (const float*)d_in[6];
    float* out = (float*)d_out;

    precompute_kernel<<<DN, 256>>>(W1, adj_logits);

    size_t smem_bytes = (size_t)DN * ROWS * 8 + 2 * CHJ * HN * 4;  // 160 KB
    cudaFuncSetAttribute(scm_kernel, cudaFuncAttributeMaxDynamicSharedMemorySize,
                         (int)smem_bytes);
    scm_kernel<<<NBLOCKS, THREADS, smem_bytes>>>(noise, b1, W2, b2, log_sigma, out);
}

// round 6
// speedup vs baseline: 1.5689x; 1.5689x over previous
#include <cuda_runtime.h>
#include <cuda_bf16.h>
#include <cstdint>

#define DN 256          // nodes
#define HN 64           // hidden
#define BN 8192         // batch
#define ROWS 64         // rows per CTA
#define THREADS 512     // 16 warps
#define NBLOCKS (BN / ROWS)   // 128
#define CHJ 32          // j-chunk
#define ZS 260          // z row stride in floats (bank + 16B-align safe)
#define WS 36           // weight tile row stride in floats

typedef unsigned long long u64;

// Masked weights in NATIVE W1 layout: g_W[i][k][j] = W1[i,k,j] * sigmoid(adj[j,i]) * (j!=i)
__device__ __align__(256) float g_W[(size_t)DN * HN * DN];   // 16.8 MB

__device__ __forceinline__ void unpack2(u64 v, float& lo, float& hi) {
    asm("mov.b64 {%0, %1}, %2;" : "=f"(lo), "=f"(hi) : "l"(v));
}
__device__ __forceinline__ u64 fma2(u64 a, u64 b, u64 c) {
    u64 d;
    asm("fma.rn.f32x2 %0, %1, %2, %3;" : "=l"(d) : "l"(a), "l"(b), "l"(c));
    return d;
}
__device__ __forceinline__ void cp_async16(void* smem_dst, const void* gsrc) {
    uint32_t s = (uint32_t)__cvta_generic_to_shared(smem_dst);
    asm volatile("cp.async.cg.shared.global [%0], [%1], 16;"
                 :: "r"(s), "l"(gsrc) : "memory");
}
__device__ __forceinline__ void cp_commit() {
    asm volatile("cp.async.commit_group;" ::: "memory");
}
__device__ __forceinline__ void cp_wait_all() {
    asm volatile("cp.async.wait_group 0;" ::: "memory");
}

__device__ __forceinline__ int nch_of(int i) {   // 32-j chunks for node i
    int jmax = (i + 3) & ~3;
    return (jmax + CHJ - 1) >> 5;                // i=0 -> 0
}

// ---------------- precompute: pure elementwise mask (no transpose) ----------------
__global__ void precompute_kernel(const float* __restrict__ W1,
                                  const float* __restrict__ adj_logits) {
    int i = blockIdx.x;
    __shared__ float asig[DN];
    for (int j = threadIdx.x; j < DN; j += blockDim.x) {
        float l = adj_logits[j * DN + i];
        float s = 1.0f / (1.0f + __expf(-l));
        asig[j] = (j == i) ? 0.0f : s;
    }
    __syncthreads();
    const float* src = W1 + (size_t)i * HN * DN;
    float* dst = g_W + (size_t)i * HN * DN;
    for (int idx = threadIdx.x; idx < HN * DN; idx += blockDim.x)
        dst[idx] = src[idx] * asig[idx & (DN - 1)];
}

// ---------------- main kernel ----------------
// Warp wid: half = wid>>3 (row half of 32), kc = wid&7 (k-chunk of 8).
// Lane: ri = lane&7 (rows rbase+8q, q=0..3), ki = lane>>3 (k = kb+ki, kb+ki+4).
// Inner loop per j-quad: 4 z LDS.128 (row-major, conflict-free) +
// 2 w LDS.128 (k-major, conflict-free) + 16 FFMA2. acc pairs live in j-parity;
// lo+hi summed once per node.
//
// smem: z float[64][ZS] | Wt float[2][HN][WS] | red float[8][64]
extern __shared__ float smem_f[];

__global__ void __launch_bounds__(THREADS, 1)
scm_kernel(const float* __restrict__ noise,
           const float* __restrict__ b1,
           const float* __restrict__ W2,
           const float* __restrict__ b2,
           const float* __restrict__ log_sigma,
           float* __restrict__ out) {
    float* z_s = smem_f;                         // [64][ZS]
    float* smw = smem_f + 64 * ZS;               // 2 x [HN][WS]
    float* red = smw + 2 * HN * WS;              // [8][64]

    const int tid  = threadIdx.x;
    const int lane = tid & 31;
    const int wid  = tid >> 5;          // 0..15
    const int half = wid >> 3;          // 0/1
    const int kb   = (wid & 7) * 8;     // warp's k-chunk base
    const int ri   = lane & 7;
    const int ki   = lane >> 3;         // 0..3
    const int k0   = kb + ki;
    const int k1   = kb + ki + 4;
    const int rbase = half * 32 + ri;   // rows rbase + 8q
    const int row0 = blockIdx.x * ROWS;

    // zero z (incl. padding) — padded j-columns >= i must read as zero
    for (int idx = tid; idx < 64 * ZS; idx += THREADS) z_s[idx] = 0.0f;
    __syncthreads();

    // prefetch tile (node 1, chunk 0) -> buffer 0.  One 16B piece per thread:
    // k = tid>>3 (64 rows), m = tid&7 (8 x 4 floats covers 32 j).
    {
        const float* src = g_W + (size_t)1 * HN * DN + (tid >> 3) * DN + (tid & 7) * 4;
        float* dst = smw + (tid >> 3) * WS + (tid & 7) * 4;
        cp_async16(dst, src);
        cp_commit();
    }
    int pi = 2, pc = 0;    // generator already past tile (1,0): nch_of(1)==1
    int pb = 1, cb = 0;

    const int wk0 = k0 * WS;
    const int wk1 = k1 * WS;

    for (int i = 0; i < DN; ++i) {
        const int nch = nch_of(i);

        // node params (latency hidden under j-loop)
        float b1v0 = __ldg(b1 + i * HN + k0);
        float b1v1 = __ldg(b1 + i * HN + k1);
        float w2v0 = __ldg(W2 + i * HN + k0);
        float w2v1 = __ldg(W2 + i * HN + k1);
        float b2v  = __ldg(b2 + i);
        float sigv = __expf(__ldg(log_sigma + i));
        float nv   = 0.0f;
        if (tid < ROWS)
            nv = __ldg(noise + (size_t)(row0 + tid) * DN + i);

        u64 acc[4][2];
        #pragma unroll
        for (int q = 0; q < 4; ++q) { acc[q][0] = 0ull; acc[q][1] = 0ull; }

        for (int c = 0; c < nch; ++c) {
            cp_wait_all();
            __syncthreads();        // tile (i,c) ready in buffer cb;
                                    // c==0 also publishes z column i-1

            if (pi < DN) {          // prefetch next stream tile
                const float* src = g_W + ((size_t)pi * HN + (tid >> 3)) * DN
                                   + pc * CHJ + (tid & 7) * 4;
                float* dst = smw + pb * (HN * WS) + (tid >> 3) * WS + (tid & 7) * 4;
                cp_async16(dst, src);
                pc++; if (pc >= nch_of(pi)) { pi++; pc = 0; }
                pb ^= 1;
            }
            cp_commit();

            const float* Wt = smw + cb * (HN * WS);
            const float* zrow = z_s + rbase * ZS + c * CHJ;
            cb ^= 1;

            #pragma unroll 4
            for (int jq = 0; jq < CHJ / 4; ++jq) {
                const int j = jq * 4;
                ulonglong2 za = *(const ulonglong2*)(zrow + j);
                ulonglong2 zb = *(const ulonglong2*)(zrow + 8 * ZS + j);
                ulonglong2 zc = *(const ulonglong2*)(zrow + 16 * ZS + j);
                ulonglong2 zq4 = *(const ulonglong2*)(zrow + 24 * ZS + j);
                ulonglong2 wa = *(const ulonglong2*)(Wt + wk0 + j);
                ulonglong2 wb = *(const ulonglong2*)(Wt + wk1 + j);
                acc[0][0] = fma2(za.x,  wa.x, acc[0][0]);
                acc[0][0] = fma2(za.y,  wa.y, acc[0][0]);
                acc[0][1] = fma2(za.x,  wb.x, acc[0][1]);
                acc[0][1] = fma2(za.y,  wb.y, acc[0][1]);
                acc[1][0] = fma2(zb.x,  wa.x, acc[1][0]);
                acc[1][0] = fma2(zb.y,  wa.y, acc[1][0]);
                acc[1][1] = fma2(zb.x,  wb.x, acc[1][1]);
                acc[1][1] = fma2(zb.y,  wb.y, acc[1][1]);
                acc[2][0] = fma2(zc.x,  wa.x, acc[2][0]);
                acc[2][0] = fma2(zc.y,  wa.y, acc[2][0]);
                acc[2][1] = fma2(zc.x,  wb.x, acc[2][1]);
                acc[2][1] = fma2(zc.y,  wb.y, acc[2][1]);
                acc[3][0] = fma2(zq4.x, wa.x, acc[3][0]);
                acc[3][0] = fma2(zq4.y, wa.y, acc[3][0]);
                acc[3][1] = fma2(zq4.x, wb.x, acc[3][1]);
                acc[3][1] = fma2(zq4.y, wb.y, acc[3][1]);
            }
        }

        // epilogue: x = acc.lo + acc.hi + b1; h = silu(x); dot w2 over lane's 2 k;
        // butterfly over ki (lane bits 3,4); cross-warp over 8 k-chunks via red.
        float s[4];
        #pragma unroll
        for (int q = 0; q < 4; ++q) {
            float e0, o0, e1, o1;
            unpack2(acc[q][0], e0, o0);
            unpack2(acc[q][1], e1, o1);
            float x0 = e0 + o0 + b1v0;
            float x1 = e1 + o1 + b1v1;
            float sv = __fdividef(x0, 1.0f + __expf(-x0)) * w2v0
                     + __fdividef(x1, 1.0f + __expf(-x1)) * w2v1;
            sv += __shfl_xor_sync(0xffffffffu, sv, 8);
            sv += __shfl_xor_sync(0xffffffffu, sv, 16);
            s[q] = sv;
        }
        if (ki == 0) {
            #pragma unroll
            for (int q = 0; q < 4; ++q)
                red[(wid & 7) * 64 + rbase + 8 * q] = s[q];
        }
        __syncthreads();            // all j-loop reads + red writes done

        if (tid < ROWS) {
            float t = red[tid];
            #pragma unroll
            for (int w = 1; w < 8; ++w) t += red[w * 64 + tid];
            z_s[tid * ZS + i] = t + b2v + sigv * nv;   // z[row][i]
        }
        // next node's c==0 cp_wait+sync publishes column i (i=0 has nch=0,
        // but node 1 has nch=1, so the sync always exists before first read)
    }

    __syncthreads();   // publish final columns

    // output: row-major z -> global coalesced
    for (int idx = tid; idx < ROWS * DN; idx += THREADS) {
        int r = idx >> 8;        // 0..63
        int j = idx & 255;       // 0..255
        out[(size_t)(row0 + r) * DN + j] = z_s[r * ZS + j];
    }
}

extern "C" void kernel_launch(void* const* d_in, const int* in_sizes, int n_in,
                              void* d_out, int out_size) {
    const float* noise      = (const float*)d_in[0];
    const float* adj_logits = (const float*)d_in[1];
    const float* W1         = (const float*)d_in[2];
    const float* b1         = (const float*)d_in[3];
    const float* W2         = (const float*)d_in[4];
    const float* b2         = (const float*)d_in[5];
    const float* log_sigma  = (const float*)d_in[6];
    float* out = (float*)d_out;

    precompute_kernel<<<DN, 256>>>(W1, adj_logits);

    size_t smem_bytes = (size_t)(64 * ZS + 2 * HN * WS + 8 * 64) * sizeof(float); // ~87 KB
    cudaFuncSetAttribute(scm_kernel, cudaFuncAttributeMaxDynamicSharedMemorySize,
                         (int)smem_bytes);
    scm_kernel<<<NBLOCKS, THREADS, smem_bytes>>>(noise, b1, W2, b2, log_sigma, out);
}

// round 8
// speedup vs baseline: 5.3727x; 3.4245x over previous
#include <cuda_runtime.h>
#include <cuda_bf16.h>
#include <cstdint>

#define DN 256
#define HN 64
#define BN 8192
#define ROWS 64
#define THREADS 256
#define NBLOCKS (BN / ROWS)   // 128

// smem byte layout
#define ZSTRB 528             // z plane row stride (264 bf16)
#define Z_H_OFF 0             // zh [64 rows][264] bf16
#define Z_L_OFF 33792         // zl
#define WT_OFF  67584         // weight ring: 2 bufs x (2 planes x 64h x 144B)
#define WT_BUF  18432
#define WT_PLANE 9216
#define RED_OFF 104448        // [2][64] f32
#define B1S_OFF 104960        // 64 f32
#define W2S_OFF 105216        // 64 f32
#define SMEM_TOTAL 105472

typedef unsigned long long u64;

// Streaming weight tiles: [i][chunk 4][plane 2][h 64][j 64] bf16 (16.8 MB, L2-resident)
// plane 0 = bf16 hi, plane 1 = bf16 lo of W1[i,k,j]*sigmoid(adj[j,i])*(j!=i)
__device__ __align__(256) __nv_bfloat16 g_Wc[(size_t)DN * 4 * 2 * 64 * 64];

// ---------------- helpers ----------------
__device__ __forceinline__ uint32_t smem_u32(const void* p) {
    uint32_t a;
    asm("{ .reg .u64 t; cvta.to.shared.u64 t, %1; cvt.u32.u64 %0, t; }"
        : "=r"(a) : "l"(p));
    return a;
}
__device__ __forceinline__ void cp16(uint32_t sdst, const void* g) {
    asm volatile("cp.async.cg.shared.global [%0], [%1], 16;"
                 :: "r"(sdst), "l"(g) : "memory");
}
#define CP_COMMIT() asm volatile("cp.async.commit_group;" ::: "memory")
#define CP_WAIT0()  asm volatile("cp.async.wait_group 0;" ::: "memory")

__device__ __forceinline__ void ldsm4(uint32_t* r, uint32_t a) {
    asm volatile("ldmatrix.sync.aligned.m8n8.x4.shared.b16 {%0,%1,%2,%3}, [%4];"
                 : "=r"(r[0]), "=r"(r[1]), "=r"(r[2]), "=r"(r[3]) : "r"(a));
}
__device__ __forceinline__ void mma_bf16(float* c, const uint32_t* a,
                                         uint32_t b0, uint32_t b1) {
    asm volatile(
        "mma.sync.aligned.m16n8k16.row.col.f32.bf16.bf16.f32 "
        "{%0,%1,%2,%3}, {%4,%5,%6,%7}, {%8,%9}, {%0,%1,%2,%3};"
        : "+f"(c[0]), "+f"(c[1]), "+f"(c[2]), "+f"(c[3])
        : "r"(a[0]), "r"(a[1]), "r"(a[2]), "r"(a[3]), "r"(b0), "r"(b1));
}
__device__ __forceinline__ int nch_of(int i) {     // 64-j chunks, i >= 1
    return ((((i + 15) & ~15) + 63) >> 6);
}

// ---------------- precompute: mask + bf16 hi/lo tile images ----------------
__global__ void precompute_kernel(const float* __restrict__ W1,
                                  const float* __restrict__ adj_logits) {
    int i = blockIdx.x;
    __shared__ float asig[DN];
    for (int j = threadIdx.x; j < DN; j += blockDim.x) {
        float l = adj_logits[j * DN + i];
        float s = 1.0f / (1.0f + __expf(-l));
        asig[j] = (j == i) ? 0.0f : s;
    }
    __syncthreads();
    const float* W1i = W1 + (size_t)i * HN * DN;
    for (int idx = threadIdx.x; idx < HN * DN; idx += blockDim.x) {
        int k = idx >> 8, j = idx & 255;
        float w = W1i[idx] * asig[j];
        __nv_bfloat16 hi = __float2bfloat16(w);
        __nv_bfloat16 lo = __float2bfloat16(w - __bfloat162float(hi));
        size_t o = ((size_t)i * 4 + (j >> 6)) * 8192 + (size_t)k * 64 + (j & 63);
        g_Wc[o]        = hi;   // plane 0
        g_Wc[o + 4096] = lo;   // plane 1
    }
}

// ---------------- main kernel ----------------
// Warp grid: wm = wid&3 -> m-tile (16 rows at m0=16*wm); wn = wid>>2 -> n-half
// (32 hidden cols at h0=32*wn).  Per k16 slice per warp: ldmatrix A hi/lo (2 x4)
// + ldmatrix B hi/lo (4 x4) + 12 mma (hh, hl, lh passes into one fp32 acc).
extern __shared__ char smem[];

__global__ void __launch_bounds__(THREADS, 1)
scm_mma_kernel(const float* __restrict__ noise,
               const float* __restrict__ b1,
               const float* __restrict__ W2,
               const float* __restrict__ b2,
               const float* __restrict__ log_sigma,
               float* __restrict__ out) {
    const uint32_t sb = smem_u32(smem);
    const int tid = threadIdx.x, lane = tid & 31, wid = tid >> 5;
    const int wm = wid & 3, wn = wid >> 2;
    const int m0 = wm * 16, h0 = wn * 32;
    const int row0 = blockIdx.x * ROWS;
    float* b1s = (float*)(smem + B1S_OFF);
    float* w2s = (float*)(smem + W2S_OFF);
    float* red = (float*)(smem + RED_OFF);

    // zero z planes (both hi and lo, 67584 B)
    for (int idx = tid; idx < 67584 / 8; idx += THREADS) ((u64*)smem)[idx] = 0ull;
    __syncthreads();

    // lane-level ldmatrix address pieces
    const uint32_t a_lane = (uint32_t)(m0 + (lane & 15)) * ZSTRB
                          + (((lane >> 4) & 1) << 4);
    const uint32_t zh_base = sb + Z_H_OFF + a_lane;
    const uint32_t zl_base = sb + Z_L_OFF + a_lane;
    const uint32_t b_lane = (uint32_t)(h0 + ((lane >> 4) << 3) + (lane & 7)) * 144
                          + (((lane >> 3) & 1) << 4);

    // initial prefetch: tile (node 1, chunk 0) -> buf 0
    {
        const char* g = (const char*)g_Wc + (size_t)4 * 16384;
        int p = tid;
        #pragma unroll
        for (int n = 0; n < 4; ++n, p += THREADS) {
            uint32_t dst = sb + WT_OFF +
                (uint32_t)((p >> 9) * WT_PLANE + ((p >> 3) & 63) * 144 + (p & 7) * 16);
            cp16(dst, g + (size_t)p * 16);
        }
        CP_COMMIT();
    }
    int pi = 2, pc = 0, pb = 1, cb = 0;   // nch_of(1)==1, so generator is at (2,0)

    for (int i = 0; i < DN; ++i) {
        const int kpad = (i + 15) & ~15;
        const int nchk = (kpad + 63) >> 6;   // 0 for i==0

        // stage per-node params
        if (tid < 64)       b1s[tid]      = b1[i * HN + tid];
        else if (tid < 128) w2s[tid - 64] = W2[i * HN + tid - 64];
        float nv = 0.f, b2v = 0.f, sigv = 0.f;
        if (tid < 64) {
            nv   = __ldg(noise + (size_t)(row0 + tid) * DN + i);
            b2v  = __ldg(b2 + i);
            sigv = __expf(__ldg(log_sigma + i));
        }
        float acc[4][4] = {};
        if (nchk == 0) __syncthreads();     // publish staging (i == 0 only)

        for (int c = 0; c < nchk; ++c) {
            CP_WAIT0();
            __syncthreads();    // tile ready in buf cb; z col i-1 published (c==0)

            if (pi < DN) {      // prefetch next stream tile -> buf pb
                const char* g = (const char*)g_Wc + ((size_t)pi * 4 + pc) * 16384;
                uint32_t bbase = sb + WT_OFF + (uint32_t)pb * WT_BUF;
                int p = tid;
                #pragma unroll
                for (int n = 0; n < 4; ++n, p += THREADS) {
                    uint32_t dst = bbase +
                        (uint32_t)((p >> 9) * WT_PLANE + ((p >> 3) & 63) * 144 + (p & 7) * 16);
                    cp16(dst, g + (size_t)p * 16);
                }
                pc++; if (pc >= nch_of(pi)) { pi++; pc = 0; }
                pb ^= 1;
            }
            CP_COMMIT();

            const uint32_t wb = sb + WT_OFF + (uint32_t)cb * WT_BUF + b_lane;
            cb ^= 1;
            const int jcend = min(kpad - 64 * c, 64);

            #pragma unroll 4
            for (int jc = 0; jc < jcend; jc += 16) {
                const uint32_t jg2 = (uint32_t)(64 * c + jc) * 2;
                uint32_t ah[4], al[4], bh[8], bl[8];
                ldsm4(ah, zh_base + jg2);
                ldsm4(al, zl_base + jg2);
                ldsm4(bh,     wb + jc * 2);                       // ntiles 0,1 hi
                ldsm4(bh + 4, wb + 2304 + jc * 2);                // ntiles 2,3 hi
                ldsm4(bl,     wb + WT_PLANE + jc * 2);            // lo
                ldsm4(bl + 4, wb + WT_PLANE + 2304 + jc * 2);
                #pragma unroll
                for (int nt = 0; nt < 4; ++nt) {
                    mma_bf16(acc[nt], ah, bh[2 * nt], bh[2 * nt + 1]);  // hh
                    mma_bf16(acc[nt], ah, bl[2 * nt], bl[2 * nt + 1]);  // hl
                    mma_bf16(acc[nt], al, bh[2 * nt], bh[2 * nt + 1]);  // lh
                }
            }
        }

        // epilogue: silu + dot(w2) over this warp's n32, reduce in-quad,
        // then cross-warp (2 n-halves) via red.
        float s_lo = 0.f, s_hi = 0.f;
        #pragma unroll
        for (int nt = 0; nt < 4; ++nt) {
            int hc = h0 + 8 * nt + 2 * (lane & 3);
            float ba = b1s[hc], bbv = b1s[hc + 1];
            float wa = w2s[hc], wbv = w2s[hc + 1];
            float x;
            x = acc[nt][0] + ba;  s_lo += __fdividef(x, 1.f + __expf(-x)) * wa;
            x = acc[nt][1] + bbv; s_lo += __fdividef(x, 1.f + __expf(-x)) * wbv;
            x = acc[nt][2] + ba;  s_hi += __fdividef(x, 1.f + __expf(-x)) * wa;
            x = acc[nt][3] + bbv; s_hi += __fdividef(x, 1.f + __expf(-x)) * wbv;
        }
        s_lo += __shfl_xor_sync(0xffffffffu, s_lo, 1);
        s_lo += __shfl_xor_sync(0xffffffffu, s_lo, 2);
        s_hi += __shfl_xor_sync(0xffffffffu, s_hi, 1);
        s_hi += __shfl_xor_sync(0xffffffffu, s_hi, 2);
        if ((lane & 3) == 0) {
            red[wn * 64 + m0 + (lane >> 2)]     = s_lo;   // row m0 + lane/4
            red[wn * 64 + m0 + 8 + (lane >> 2)] = s_hi;   // row m0 + 8 + lane/4
        }
        __syncthreads();

        if (tid < 64) {
            float val = red[tid] + red[64 + tid] + b2v + sigv * nv;
            out[(size_t)(row0 + tid) * DN + i] = val;
            __nv_bfloat16 zh = __float2bfloat16(val);
            __nv_bfloat16 zl = __float2bfloat16(val - __bfloat162float(zh));
            *(__nv_bfloat16*)(smem + Z_H_OFF + tid * ZSTRB + i * 2) = zh;
            *(__nv_bfloat16*)(smem + Z_L_OFF + tid * ZSTRB + i * 2) = zl;
        }
        // next node's chunk-0 CP_WAIT0 + __syncthreads publishes z col i
    }
}

extern "C" void kernel_launch(void* const* d_in, const int* in_sizes, int n_in,
                              void* d_out, int out_size) {
    const float* noise      = (const float*)d_in[0];
    const float* adj_logits = (const float*)d_in[1];
    const float* W1         = (const float*)d_in[2];
    const float* b1         = (const float*)d_in[3];
    const float* W2         = (const float*)d_in[4];
    const float* b2         = (const float*)d_in[5];
    const float* log_sigma  = (const float*)d_in[6];
    float* out = (float*)d_out;

    precompute_kernel<<<DN, 256>>>(W1, adj_logits);

    cudaFuncSetAttribute(scm_mma_kernel, cudaFuncAttributeMaxDynamicSharedMemorySize,
                         SMEM_TOTAL);
    scm_mma_kernel<<<NBLOCKS, THREADS, SMEM_TOTAL>>>(noise, b1, W2, b2,
                                                     log_sigma, out);
}

// round 9
// speedup vs baseline: 5.4144x; 1.0077x over previous
#include <cuda_runtime.h>
#include <cuda_bf16.h>
#include <cstdint>

#define DN 256
#define HN 64
#define BN 8192
#define ROWS 64
#define THREADS 256
#define NBLOCKS (BN / ROWS)   // 128

// smem byte layout
#define ZSTRB 528             // z plane row stride (264 bf16)
#define Z_H_OFF 0             // zh [64 rows][264] bf16
#define Z_L_OFF 33792         // zl
#define WT_OFF  67584         // weight ring: 3 bufs x (2 planes x 64h x 144B)
#define WT_BUF  18432
#define WT_PLANE 9216
#define RED_OFF 122880        // [2][64] f32
#define B1S_OFF 123392        // 64 f32
#define W2S_OFF 123648        // 64 f32
#define SMEM_TOTAL 123904

typedef unsigned long long u64;

// Streaming weight tiles: [i][chunk 4][plane 2][h 64][j 64] bf16 (16.8 MB, L2-resident)
__device__ __align__(256) __nv_bfloat16 g_Wc[(size_t)DN * 4 * 2 * 64 * 64];

// ---------------- helpers ----------------
__device__ __forceinline__ uint32_t smem_u32(const void* p) {
    uint32_t a;
    asm("{ .reg .u64 t; cvta.to.shared.u64 t, %1; cvt.u32.u64 %0, t; }"
        : "=r"(a) : "l"(p));
    return a;
}
__device__ __forceinline__ void cp16(uint32_t sdst, const void* g) {
    asm volatile("cp.async.cg.shared.global [%0], [%1], 16;"
                 :: "r"(sdst), "l"(g) : "memory");
}
#define CP_COMMIT() asm volatile("cp.async.commit_group;" ::: "memory")
#define CP_WAIT1()  asm volatile("cp.async.wait_group 1;" ::: "memory")

__device__ __forceinline__ void ldsm4(uint32_t* r, uint32_t a) {
    asm volatile("ldmatrix.sync.aligned.m8n8.x4.shared.b16 {%0,%1,%2,%3}, [%4];"
                 : "=r"(r[0]), "=r"(r[1]), "=r"(r[2]), "=r"(r[3]) : "r"(a));
}
__device__ __forceinline__ void mma_bf16(float* c, const uint32_t* a,
                                         uint32_t b0, uint32_t b1) {
    asm volatile(
        "mma.sync.aligned.m16n8k16.row.col.f32.bf16.bf16.f32 "
        "{%0,%1,%2,%3}, {%4,%5,%6,%7}, {%8,%9}, {%0,%1,%2,%3};"
        : "+f"(c[0]), "+f"(c[1]), "+f"(c[2]), "+f"(c[3])
        : "r"(a[0]), "r"(a[1]), "r"(a[2]), "r"(a[3]), "r"(b0), "r"(b1));
}
__device__ __forceinline__ int nch_of(int i) {
    return ((((i + 15) & ~15) + 63) >> 6);
}
// cp.async dest offset for linear piece p (0..1023) within a tile buffer
__device__ __forceinline__ uint32_t wt_dst(int p) {
    return (uint32_t)((p >> 9) * WT_PLANE + ((p >> 3) & 63) * 144 + (p & 7) * 16);
}

// ---------------- precompute: mask + bf16 hi/lo tile images ----------------
__global__ void precompute_kernel(const float* __restrict__ W1,
                                  const float* __restrict__ adj_logits) {
    int i = blockIdx.x;
    __shared__ float asig[DN];
    for (int j = threadIdx.x; j < DN; j += blockDim.x) {
        float l = adj_logits[j * DN + i];
        float s = 1.0f / (1.0f + __expf(-l));
        asig[j] = (j == i) ? 0.0f : s;
    }
    __syncthreads();
    const float* W1i = W1 + (size_t)i * HN * DN;
    for (int idx = threadIdx.x; idx < HN * DN; idx += blockDim.x) {
        int k = idx >> 8, j = idx & 255;
        float w = W1i[idx] * asig[j];
        __nv_bfloat16 hi = __float2bfloat16(w);
        __nv_bfloat16 lo = __float2bfloat16(w - __bfloat162float(hi));
        size_t o = ((size_t)i * 4 + (j >> 6)) * 8192 + (size_t)k * 64 + (j & 63);
        g_Wc[o]        = hi;   // plane 0
        g_Wc[o + 4096] = lo;   // plane 1
    }
}

// ---------------- main kernel ----------------
extern __shared__ char smem[];

__global__ void __launch_bounds__(THREADS, 1)
scm_mma_kernel(const float* __restrict__ noise,
               const float* __restrict__ b1,
               const float* __restrict__ W2,
               const float* __restrict__ b2,
               const float* __restrict__ log_sigma,
               float* __restrict__ out) {
    const uint32_t sb = smem_u32(smem);
    const int tid = threadIdx.x, lane = tid & 31, wid = tid >> 5;
    const int wm = wid & 3, wn = wid >> 2;
    const int m0 = wm * 16, h0 = wn * 32;
    const int row0 = blockIdx.x * ROWS;
    float* b1s = (float*)(smem + B1S_OFF);
    float* w2s = (float*)(smem + W2S_OFF);
    float* red = (float*)(smem + RED_OFF);

    // zero z planes
    for (int idx = tid; idx < 67584 / 8; idx += THREADS) ((u64*)smem)[idx] = 0ull;
    __syncthreads();

    const uint32_t a_lane = (uint32_t)(m0 + (lane & 15)) * ZSTRB
                          + (((lane >> 4) & 1) << 4);
    const uint32_t zh_base = sb + Z_H_OFF + a_lane;
    const uint32_t zl_base = sb + Z_L_OFF + a_lane;
    const uint32_t b_lane = (uint32_t)(h0 + ((lane >> 4) << 3) + (lane & 7)) * 144
                          + (((lane >> 3) & 1) << 4);

    // prime ring: tile (1,0) -> slot 0, tile (2,0) -> slot 1 (two commit groups)
    {
        const char* g1 = (const char*)g_Wc + (size_t)4 * 16384;
        int p = tid;
        #pragma unroll
        for (int n = 0; n < 4; ++n, p += THREADS)
            cp16(sb + WT_OFF + wt_dst(p), g1 + (size_t)p * 16);
        CP_COMMIT();
        const char* g2 = (const char*)g_Wc + (size_t)8 * 16384;
        p = tid;
        #pragma unroll
        for (int n = 0; n < 4; ++n, p += THREADS)
            cp16(sb + WT_OFF + WT_BUF + wt_dst(p), g2 + (size_t)p * 16);
        CP_COMMIT();
    }
    int pi = 3, pc = 0;        // generator past (1,0),(2,0)
    int np_slot = 2, cs = 0;   // next prefetch slot / consume slot

    for (int i = 0; i < DN; ++i) {
        const int kpad = (i + 15) & ~15;
        const int nchk = (kpad + 63) >> 6;   // 0 for i==0

        // stage per-node params
        if (tid < 64)       b1s[tid]      = b1[i * HN + tid];
        else if (tid < 128) w2s[tid - 64] = W2[i * HN + tid - 64];
        float nv = 0.f, b2v = 0.f, sigv = 0.f;
        if (tid < 64) {
            nv   = __ldg(noise + (size_t)(row0 + tid) * DN + i);
            b2v  = __ldg(b2 + i);
            sigv = __expf(__ldg(log_sigma + i));
        }
        float acc[4][4] = {}, acc2[4][4] = {};
        if (nchk == 0) __syncthreads();     // publish staging (i == 0 only)

        for (int c = 0; c < nchk; ++c) {
            CP_WAIT1();          // oldest outstanding group (this tile) done
            __syncthreads();     // tile visible to all; z col i-1 published (c==0)

            if (pi < DN) {       // prefetch 2-ahead into np_slot
                const char* g = (const char*)g_Wc + ((size_t)pi * 4 + pc) * 16384;
                uint32_t bbase = sb + WT_OFF + (uint32_t)np_slot * WT_BUF;
                int p = tid;
                #pragma unroll
                for (int n = 0; n < 4; ++n, p += THREADS)
                    cp16(bbase + wt_dst(p), g + (size_t)p * 16);
                pc++; if (pc >= nch_of(pi)) { pi++; pc = 0; }
                np_slot = (np_slot == 2) ? 0 : np_slot + 1;
            }
            CP_COMMIT();

            const uint32_t wb = sb + WT_OFF + (uint32_t)cs * WT_BUF + b_lane;
            cs = (cs == 2) ? 0 : cs + 1;
            const int jcend = min(kpad - 64 * c, 64);

            auto do_slice = [&](int jc, float (*ac)[4]) {
                const uint32_t jg2 = (uint32_t)(64 * c + jc) * 2;
                uint32_t ah[4], al[4], bh[8], bl[8];
                ldsm4(ah, zh_base + jg2);
                ldsm4(al, zl_base + jg2);
                ldsm4(bh,     wb + jc * 2);
                ldsm4(bh + 4, wb + 2304 + jc * 2);
                ldsm4(bl,     wb + WT_PLANE + jc * 2);
                ldsm4(bl + 4, wb + WT_PLANE + 2304 + jc * 2);
                #pragma unroll
                for (int nt = 0; nt < 4; ++nt) {
                    mma_bf16(ac[nt], ah, bh[2 * nt], bh[2 * nt + 1]);  // hh
                    mma_bf16(ac[nt], ah, bl[2 * nt], bl[2 * nt + 1]);  // hl
                    mma_bf16(ac[nt], al, bh[2 * nt], bh[2 * nt + 1]);  // lh
                }
            };
            #pragma unroll 2
            for (int jc = 0; jc < jcend; jc += 32) {
                do_slice(jc, acc);                          // even slice
                if (jc + 16 < jcend) do_slice(jc + 16, acc2);  // odd slice
            }
        }

        // epilogue: merge acc banks, silu + dot(w2), quad reduce, cross-half red
        float s_lo = 0.f, s_hi = 0.f;
        #pragma unroll
        for (int nt = 0; nt < 4; ++nt) {
            int hc = h0 + 8 * nt + 2 * (lane & 3);
            float ba = b1s[hc], bbv = b1s[hc + 1];
            float wa = w2s[hc], wbv = w2s[hc + 1];
            float x;
            x = acc[nt][0] + acc2[nt][0] + ba;
            s_lo += __fdividef(x, 1.f + __expf(-x)) * wa;
            x = acc[nt][1] + acc2[nt][1] + bbv;
            s_lo += __fdividef(x, 1.f + __expf(-x)) * wbv;
            x = acc[nt][2] + acc2[nt][2] + ba;
            s_hi += __fdividef(x, 1.f + __expf(-x)) * wa;
            x = acc[nt][3] + acc2[nt][3] + bbv;
            s_hi += __fdividef(x, 1.f + __expf(-x)) * wbv;
        }
        s_lo += __shfl_xor_sync(0xffffffffu, s_lo, 1);
        s_lo += __shfl_xor_sync(0xffffffffu, s_lo, 2);
        s_hi += __shfl_xor_sync(0xffffffffu, s_hi, 1);
        s_hi += __shfl_xor_sync(0xffffffffu, s_hi, 2);
        if ((lane & 3) == 0) {
            red[wn * 64 + m0 + (lane >> 2)]     = s_lo;
            red[wn * 64 + m0 + 8 + (lane >> 2)] = s_hi;
        }
        __syncthreads();

        if (tid < 64) {
            float val = red[tid] + red[64 + tid] + b2v + sigv * nv;
            __nv_bfloat16 zh = __float2bfloat16(val);
            __nv_bfloat16 zl = __float2bfloat16(val - __bfloat162float(zh));
            *(__nv_bfloat16*)(smem + Z_H_OFF + tid * ZSTRB + i * 2) = zh;
            *(__nv_bfloat16*)(smem + Z_L_OFF + tid * ZSTRB + i * 2) = zl;
        }
        // next node's chunk-0 sync publishes z col i
    }

    __syncthreads();   // publish final z columns
    // coalesced output: out = zh + zl (reconstruction err ~2^-17, negligible)
    for (int idx = tid; idx < ROWS * DN; idx += THREADS) {
        int r = idx >> 8, j = idx & 255;
        float zh = __bfloat162float(
            *(const __nv_bfloat16*)(smem + Z_H_OFF + r * ZSTRB + j * 2));
        float zl = __bfloat162float(
            *(const __nv_bfloat16*)(smem + Z_L_OFF + r * ZSTRB + j * 2));
        out[(size_t)(row0 + r) * DN + j] = zh + zl;
    }
}

extern "C" void kernel_launch(void* const* d_in, const int* in_sizes, int n_in,
                              void* d_out, int out_size) {
    const float* noise      = (const float*)d_in[0];
    const float* adj_logits = (const float*)d_in[1];
    const float* W1         = (const float*)d_in[2];
    const float* b1         = (const float*)d_in[3];
    const float* W2         = (const float*)d_in[4];
    const float* b2         = (const float*)d_in[5];
    const float* log_sigma  = (const float*)d_in[6];
    float* out = (float*)d_out;

    precompute_kernel<<<DN, 256>>>(W1, adj_logits);

    cudaFuncSetAttribute(scm_mma_kernel, cudaFuncAttributeMaxDynamicSharedMemorySize,
                         SMEM_TOTAL);
    scm_mma_kernel<<<NBLOCKS, THREADS, SMEM_TOTAL>>>(noise, b1, W2, b2,
                                                     log_sigma, out);
}